// round 8
// baseline (speedup 1.0000x reference)
#include <cuda_runtime.h>
#include <cstdint>
#include <math.h>

#define T_TOK 8192
#define D_DIM 7168
#define E_EXP 256
#define K_TOP 8
#define G_GRP 8
#define LG_GRP 4

#define SCALE_A 1048576.0f    // 2^20
#define SCALE_B 67108864.0f   // 2^26

// GEMM tiling
#define BM 64
#define BN 64
#define NCHUNK (D_DIM / 32)   // 224 chunks of 32 k-elements

#define AROW 112              // padded smem row bytes (3 limbs x 32 + 16 pad)
#define ATILE (BM * AROW)     // 7168
#define STAGE (2 * ATILE)     // 14336 (A tile | B tile)

__device__ int8_t g_qa[3][(size_t)T_TOK * D_DIM];
__device__ int8_t g_qb[3][(size_t)E_EXP * D_DIM];
__device__ float  g_logits[(size_t)T_TOK * E_EXP];
__device__ int    g_counts[E_EXP];

__device__ __forceinline__ uint32_t smem_to_u32(const void* p) {
    uint32_t a;
    asm("{ .reg .u64 t; cvta.to.shared.u64 t, %1; cvt.u32.u64 %0, t; }" : "=r"(a) : "l"(p));
    return a;
}

#define LDSM_X4(r0, r1, r2, r3, a) \
    asm volatile("ldmatrix.sync.aligned.m8n8.x4.shared.b16 {%0,%1,%2,%3}, [%4];" \
                 : "=r"(r0), "=r"(r1), "=r"(r2), "=r"(r3) : "r"(a))

#define IMMA(c, a, b0, b1) \
    asm volatile("mma.sync.aligned.m16n8k32.row.col.s32.s8.s8.s32 " \
                 "{%0,%1,%2,%3}, {%4,%5,%6,%7}, {%8,%9}, {%0,%1,%2,%3};" \
                 : "+r"((c)[0]), "+r"((c)[1]), "+r"((c)[2]), "+r"((c)[3]) \
                 : "r"((a)[0]), "r"((a)[1]), "r"((a)[2]), "r"((a)[3]), "r"(b0), "r"(b1))

#define STS128(addr, v) \
    asm volatile("st.shared.v4.b32 [%0], {%1, %2, %3, %4};" \
                 :: "r"(addr), "r"((v).x), "r"((v).y), "r"((v).z), "r"((v).w) : "memory")

// ============ quantize: f32 -> 3 signed 8-bit limbs (exact) ============
__global__ __launch_bounds__(256)
void quant_kernel(const float* __restrict__ src, float scale, int which, int n4) {
    int i = blockIdx.x * blockDim.x + threadIdx.x;
    if (i >= n4) return;
    int8_t* ph = which ? g_qb[0] : g_qa[0];
    int8_t* pm = which ? g_qb[1] : g_qa[1];
    int8_t* pl = which ? g_qb[2] : g_qa[2];
    float4 v = ((const float4*)src)[i];
    float f[4] = {v.x, v.y, v.z, v.w};
    uint32_t bh = 0, bm = 0, bl = 0;
    #pragma unroll
    for (int j = 0; j < 4; j++) {
        float qf = f[j] * scale;
        qf = fminf(fmaxf(qf, -8388608.0f), 8355199.0f);
        int q = __float2int_rn(qf);
        int l = (int)(int8_t)q;
        int r1 = (q - l) >> 8;
        int m = (int)(int8_t)r1;
        int h = (r1 - m) >> 8;
        bl |= (uint32_t)(uint8_t)l << (8 * j);
        bm |= (uint32_t)(uint8_t)m << (8 * j);
        bh |= (uint32_t)(uint8_t)h << (8 * j);
    }
    ((uint32_t*)ph)[i] = bh;
    ((uint32_t*)pm)[i] = bm;
    ((uint32_t*)pl)[i] = bl;
}

// class id for limb pair (la, lb); la,lb in {0=h,1=m,2=l}; (2,2) excluded
__device__ __forceinline__ int cls_of(int la, int lb) {
    // weights: 0:2^32 | 1,2:2^24 | 3,4,5:2^16 | 6,7:2^8
    const int map[3][3] = { {0, 1, 4}, {2, 3, 6}, {5, 7, -1} };
    return map[la][lb];
}

// ============ GEMM: logits = x @ W^T, exact s8-limb IMMA, 8 classes ============
// Invariant: each accumulator set receives EXACTLY ONE mma.sync per chunk
// iteration (accumulation only across iterations) — the empirically safe pattern.
__global__ __launch_bounds__(256, 1)
void gemm_s8_kernel(float* __restrict__ C) {
    __shared__ __align__(16) uint8_t smem[2 * STAGE];   // 28672 B
    const uint32_t sb = smem_to_u32(smem);

    const int tid  = threadIdx.x;
    const int wid  = tid >> 5;
    const int lane = tid & 31;
    const int wm   = wid & 3;      // 4 warp-rows x 16 M
    const int wn   = wid >> 2;     // 2 warp-cols x 32 N

    const int mbase = blockIdx.y * BM;
    const int nbase = blockIdx.x * BN;

    // --- global->smem loader mapping: 768 uint4 per chunk, 3 per thread ---
    const int side = tid >> 7;          // 0 = A, 1 = B
    const int lt   = tid & 127;
    const int8_t* gp[3];
    uint32_t so[3];
    #pragma unroll
    for (int j = 0; j < 3; j++) {
        const int id   = lt * 3 + j;    // 0..383
        const int row  = id / 6;        // 0..63
        const int part = id % 6;
        const int lb   = part >> 1;
        const int hf   = part & 1;
        gp[j] = (side ? (g_qb[lb] + (size_t)(nbase + row) * D_DIM)
                      : (g_qa[lb] + (size_t)(mbase + row) * D_DIM)) + hf * 16;
        so[j] = (uint32_t)(side * ATILE + row * AROW + lb * 32 + hf * 16);
    }

    const uint32_t lm_a = (uint32_t)(wm * 16 + (lane & 15)) * AROW + (uint32_t)(lane >> 4) * 16;
    const uint32_t lm_b = (uint32_t)ATILE + (uint32_t)(wn * 32 + (lane & 15)) * AROW + (uint32_t)(lane >> 4) * 16;

    int acc[8][4][4];
    #pragma unroll
    for (int c = 0; c < 8; c++)
        #pragma unroll
        for (int j = 0; j < 4; j++)
            #pragma unroll
            for (int q = 0; q < 4; q++) acc[c][j][q] = 0;

    uint4 rv[3];

    // prologue: chunk 0 -> buf 0
    #pragma unroll
    for (int j = 0; j < 3; j++) rv[j] = *(const uint4*)(gp[j]);
    #pragma unroll
    for (int j = 0; j < 3; j++) STS128(sb + so[j], rv[j]);
    __syncthreads();
    #pragma unroll
    for (int j = 0; j < 3; j++) rv[j] = *(const uint4*)(gp[j] + 32);

    #pragma unroll 1
    for (int s = 0; s < NCHUNK; s++) {
        const uint32_t cb = sb + (uint32_t)(s & 1) * STAGE;
        const uint32_t nb = sb + (uint32_t)((s + 1) & 1) * STAGE;

        if (s + 1 < NCHUNK) {
            #pragma unroll
            for (int j = 0; j < 3; j++) STS128(nb + so[j], rv[j]);
        }
        if (s + 2 < NCHUNK) {
            const size_t k0 = (size_t)(s + 2) * 32;
            #pragma unroll
            for (int j = 0; j < 3; j++) rv[j] = *(const uint4*)(gp[j] + k0);
        }

        // A fragments: 3 limbs (one 16x32 tile each)
        uint32_t fa[3][4];
        #pragma unroll
        for (int la = 0; la < 3; la++)
            LDSM_X4(fa[la][0], fa[la][1], fa[la][2], fa[la][3],
                    cb + lm_a + (uint32_t)la * 32);

        // B-limb-major; each (la,lb) class -> its own accumulator set
        #pragma unroll
        for (int lb = 0; lb < 3; lb++) {
            uint32_t fb[2][4];
            #pragma unroll
            for (int nf = 0; nf < 2; nf++)
                LDSM_X4(fb[nf][0], fb[nf][1], fb[nf][2], fb[nf][3],
                        cb + lm_b + (uint32_t)lb * 32 + (uint32_t)nf * 16 * AROW);
            #pragma unroll
            for (int la = 0; la < 3; la++) {
                if (la == 2 && lb == 2) continue;   // drop ll (2^0, ~7e-9)
                const int cls = cls_of(la, lb);
                #pragma unroll
                for (int nbk = 0; nbk < 4; nbk++)
                    IMMA(acc[cls][nbk], fa[la],
                         fb[nbk >> 1][nbk & 1], fb[nbk >> 1][(nbk & 1) + 2]);
            }
        }
        __syncthreads();
    }

    // epilogue: exact combine in double (all class sums < 2^31; products < 2^53)
    const double S32 = 6.103515625e-5;          // 2^32 / 2^46 = 2^-14
    const double S24 = 2.384185791015625e-7;    // 2^-22
    const double S16 = 9.313225746154785e-10;   // 2^-30
    const double S08 = 3.637978807091713e-12;   // 2^-38
    const int r0 = mbase + wm * 16 + (lane >> 2);
    #pragma unroll
    for (int nbk = 0; nbk < 4; nbk++) {
        const int cc = nbase + wn * 32 + nbk * 8 + (lane & 3) * 2;
        float v[4];
        #pragma unroll
        for (int q = 0; q < 4; q++) {
            double d = (double)acc[0][nbk][q] * S32
                     + ((double)acc[1][nbk][q] + (double)acc[2][nbk][q]) * S24
                     + ((double)acc[3][nbk][q] + (double)acc[4][nbk][q] + (double)acc[5][nbk][q]) * S16
                     + ((double)acc[6][nbk][q] + (double)acc[7][nbk][q]) * S08;
            v[q] = (float)d;
        }
        *(float2*)(C + (size_t)r0 * E_EXP + cc)       = make_float2(v[0], v[1]);
        *(float2*)(C + (size_t)(r0 + 8) * E_EXP + cc) = make_float2(v[2], v[3]);
    }
}

// ================= Routing: one warp per token =================
__global__ __launch_bounds__(256)
void route_kernel(const float* __restrict__ logits,
                  const float* __restrict__ bias,
                  void* __restrict__ w_out,
                  void* __restrict__ idx_out,
                  int mode)
{
    const float NEG_INF = __int_as_float(0xff800000);
    const int warp = threadIdx.x >> 5;
    const int lane = threadIdx.x & 31;
    const int t = blockIdx.x * 8 + warp;
    if (t >= T_TOK) return;

    const float* lp = logits + (size_t)t * E_EXP;

    float s[8], v[8];
    #pragma unroll
    for (int r = 0; r < 8; r++) {
        float z = __ldg(lp + r * 32 + lane);
        float sig = 1.0f / (1.0f + expf(-z));
        s[r] = sig;
        v[r] = sig + __ldg(bias + r * 32 + lane);
    }

    float gsc[8];
    #pragma unroll
    for (int r = 0; r < 8; r++) {
        float m1 = v[r], m2 = NEG_INF;
        #pragma unroll
        for (int off = 16; off; off >>= 1) {
            float o1 = __shfl_xor_sync(0xffffffffu, m1, off);
            float o2 = __shfl_xor_sync(0xffffffffu, m2, off);
            float hi = fmaxf(m1, o1);
            float lo = fminf(m1, o1);
            m2 = fmaxf(lo, fmaxf(m2, o2));
            m1 = hi;
        }
        gsc[r] = m1 + m2;
    }

    unsigned chosen = 0;
    #pragma unroll
    for (int it = 0; it < LG_GRP; it++) {
        float best = NEG_INF; int bg = 0;
        #pragma unroll
        for (int g = 0; g < G_GRP; g++) {
            bool free_g = ((chosen >> g) & 1u) == 0u;
            if (free_g && gsc[g] > best) { best = gsc[g]; bg = g; }
        }
        chosen |= 1u << bg;
    }
    #pragma unroll
    for (int r = 0; r < 8; r++)
        if (!((chosen >> r) & 1u)) v[r] = NEG_INF;

    float my_w = 0.0f;
    int   my_e = 0;
    #pragma unroll
    for (int k = 0; k < K_TOP; k++) {
        float lb = NEG_INF; int lr = 0;
        #pragma unroll
        for (int r = 0; r < 8; r++)
            if (v[r] > lb) { lb = v[r]; lr = r; }
        float bv = lb;
        int be = lr * 32 + lane;
        #pragma unroll
        for (int off = 16; off; off >>= 1) {
            float ov = __shfl_xor_sync(0xffffffffu, bv, off);
            int   oe = __shfl_xor_sync(0xffffffffu, be, off);
            if (ov > bv || (ov == bv && oe < be)) { bv = ov; be = oe; }
        }
        const int wr = be >> 5, wl = be & 31;
        float sv_sel = 0.0f;
        #pragma unroll
        for (int r = 0; r < 8; r++)
            if (r == wr) sv_sel = s[r];
        float ws = __shfl_sync(0xffffffffu, sv_sel, wl);
        if (lane == k) { my_w = ws; my_e = be; }
        if (lane == wl) {
            #pragma unroll
            for (int r = 0; r < 8; r++)
                if (r == wr) v[r] = NEG_INF;
        }
    }

    float wsum = (lane < K_TOP) ? my_w : 0.0f;
    #pragma unroll
    for (int off = 16; off; off >>= 1)
        wsum += __shfl_xor_sync(0xffffffffu, wsum, off);
    float wfin = my_w * (2.5f / wsum);

    if (lane < K_TOP) {
        const size_t o = (size_t)t * K_TOP + lane;
        if (mode == 2) {
            ((float*)w_out)[o]   = wfin;
            ((float*)idx_out)[o] = (float)my_e;
        } else {
            ((float*)w_out)[o]       = wfin;
            ((long long*)idx_out)[o] = (long long)my_e;
        }
        atomicAdd(&g_counts[my_e], 1);
    }
}

__global__ void zero_counts_kernel() { g_counts[threadIdx.x] = 0; }

__global__ void write_counts_kernel(void* __restrict__ cnt_out, int mode) {
    const int e = threadIdx.x;
    if (mode == 2) ((float*)cnt_out)[e] = (float)g_counts[e];
    else           ((int*)cnt_out)[e]   = g_counts[e];
}

// ================= launch =================
extern "C" void kernel_launch(void* const* d_in, const int* in_sizes, int n_in,
                              void* d_out, int out_size)
{
    const float* x    = (const float*)d_in[0];
    const float* W    = (const float*)d_in[1];
    const float* bias = (const float*)d_in[2];

    char* base = (char*)d_out;
    const size_t TK = (size_t)T_TOK * K_TOP;

    int mode;
    void *w_out, *idx_out, *cnt_out;
    if (out_size == (int)(TK + TK + E_EXP)) {
        mode = 2;                      // all-f32 concat (JAX promotion, x64 off)
        w_out   = base;
        idx_out = base + TK * 4;
        cnt_out = base + 2 * TK * 4;
    } else {
        mode = 0;                      // byte-concat f32 | i64 | i32
        w_out   = base;
        idx_out = base + TK * 4;
        cnt_out = base + TK * 4 + TK * 8;
    }

    zero_counts_kernel<<<1, E_EXP>>>();

    const int nA4 = T_TOK * D_DIM / 4;
    const int nB4 = E_EXP * D_DIM / 4;
    quant_kernel<<<(nA4 + 255) / 256, 256>>>(x, SCALE_A, 0, nA4);
    quant_kernel<<<(nB4 + 255) / 256, 256>>>(W, SCALE_B, 1, nB4);

    dim3 grid(E_EXP / BN, T_TOK / BM);   // (4, 128) = 512 CTAs
    gemm_s8_kernel<<<grid, 256>>>(g_logits);

    route_kernel<<<T_TOK / 8, 256>>>(g_logits, bias, w_out, idx_out, mode);
    write_counts_kernel<<<1, E_EXP>>>(cnt_out, mode);
}

// round 9
// speedup vs baseline: 2.2206x; 2.2206x over previous
#include <cuda_runtime.h>
#include <cstdint>
#include <math.h>

#define T_TOK 8192
#define D_DIM 7168
#define E_EXP 256
#define K_TOP 8
#define G_GRP 8
#define LG_GRP 4

// ---- GEMM tiling: CTA 64(M) x 128(N), 128 threads, BK=8, double-buffered ----
#define BM 64
#define BN 128
#define BK 8
#define NSTAGE (D_DIM / BK)      // 896

#define AST 528                  // bytes per smem k-row (132 floats, 16B-aligned pad)
#define A_BYTES (BK * AST)       // 4224  (A-dup region: 64 m duplicated -> 128 floats/row)
#define B_OFF   A_BYTES          // B region follows A
#define STAGE_B (2 * A_BYTES)    // 8448 per buffer
// total smem: 2 * 8448 = 16896 B -> 2 CTAs/SM

__device__ float g_logits[(size_t)T_TOK * E_EXP];
__device__ int   g_counts[E_EXP];

__device__ __forceinline__ uint32_t smem_to_u32(const void* p) {
    uint32_t a;
    asm("{ .reg .u64 t; cvta.to.shared.u64 t, %1; cvt.u32.u64 %0, t; }" : "=r"(a) : "l"(p));
    return a;
}

// packed f32x2 FMA: d += a * b (lanewise on 64-bit packed pairs)
#define FFMA2(d, a, b) \
    asm("fma.rn.f32x2 %0, %1, %2, %0;" : "+l"(d) : "l"(a), "l"(b))

// 16B shared load as two packed-f32x2 operands
#define LDS_2U64(r0, r1, addr) \
    asm volatile("ld.shared.v2.u64 {%0, %1}, [%2];" : "=l"(r0), "=l"(r1) : "r"(addr))

// store duplicated float pair {v, v}
#define STS_DUP(addr, v) \
    asm volatile("st.shared.v2.f32 [%0], {%1, %1};" :: "r"(addr), "f"(v) : "memory")

#define STS_F32(addr, v) \
    asm volatile("st.shared.f32 [%0], %1;" :: "r"(addr), "f"(v) : "memory")

// ================= GEMM: C[t][e] = sum_k x[t][k] * W[e][k]  (exact f32) =============
__global__ __launch_bounds__(128, 2)
void gemm_f32x2_kernel(const float* __restrict__ A,   // x [T, D]
                       const float* __restrict__ B,   // W [E, D]
                       float* __restrict__ C)         // logits [T, E]
{
    __shared__ __align__(16) uint8_t smem[2 * STAGE_B];
    const uint32_t sb = smem_to_u32(smem);

    const int tid = threadIdx.x;
    const int tx  = tid & 15;        // n-group
    const int ty  = tid >> 4;        // m-group 0..7

    const int mb = blockIdx.y * BM;
    const int nb = blockIdx.x * BN;

    // ---- loader mapping ----
    // A: thread -> (m = tid>>1, k-quad = (tid&1)*4); one float4 per stage
    const int am  = tid >> 1;
    const int akq = (tid & 1) * 4;
    const float* Ag = A + (size_t)(mb + am) * D_DIM + akq;
    // B: thread -> row n = tid; two float4 (k0..3, k4..7) per stage
    const float* Bg = B + (size_t)(nb + tid) * D_DIM;

    const uint32_t a_sts = sb + (uint32_t)akq * AST + (uint32_t)am * 8u;
    const uint32_t b_sts = sb + B_OFF + (uint32_t)tid * 4u;

    // ---- compute-side smem bases ----
    const uint32_t a_lds = sb + (uint32_t)ty * 32u;          // dup'd pairs for m = ty*4.., 32+ty*4..
    const uint32_t b_lds = sb + B_OFF + (uint32_t)tx * 16u;  // cols tx*4.., 64+tx*4..

    uint64_t acc[8][4];
    #pragma unroll
    for (int i = 0; i < 8; i++)
        #pragma unroll
        for (int j = 0; j < 4; j++) acc[i][j] = 0ull;

    float4 ra, rb0, rb1;

    // ---- prologue: stage 0 -> buf 0 ----
    ra  = *(const float4*)(Ag);
    rb0 = *(const float4*)(Bg);
    rb1 = *(const float4*)(Bg + 4);
    {
        const float av[4] = {ra.x, ra.y, ra.z, ra.w};
        #pragma unroll
        for (int j = 0; j < 4; j++) STS_DUP(a_sts + (uint32_t)j * AST, av[j]);
        const float bv0[4] = {rb0.x, rb0.y, rb0.z, rb0.w};
        const float bv1[4] = {rb1.x, rb1.y, rb1.z, rb1.w};
        #pragma unroll
        for (int j = 0; j < 4; j++) {
            STS_F32(b_sts + (uint32_t)j * AST, bv0[j]);
            STS_F32(b_sts + (uint32_t)(j + 4) * AST, bv1[j]);
        }
    }
    __syncthreads();
    // prefetch stage 1
    ra  = *(const float4*)(Ag + BK);
    rb0 = *(const float4*)(Bg + BK);
    rb1 = *(const float4*)(Bg + BK + 4);

    #pragma unroll 1
    for (int s = 0; s < NSTAGE; s++) {
        const uint32_t cbo = (uint32_t)(s & 1) * STAGE_B;
        const uint32_t nbo = (uint32_t)((s + 1) & 1) * STAGE_B;

        // store stage s+1 into the other buffer (its previous contents were
        // consumed in iteration s-1, protected by the trailing sync)
        if (s + 1 < NSTAGE) {
            const float av[4] = {ra.x, ra.y, ra.z, ra.w};
            #pragma unroll
            for (int j = 0; j < 4; j++) STS_DUP(a_sts + nbo + (uint32_t)j * AST, av[j]);
            const float bv0[4] = {rb0.x, rb0.y, rb0.z, rb0.w};
            const float bv1[4] = {rb1.x, rb1.y, rb1.z, rb1.w};
            #pragma unroll
            for (int j = 0; j < 4; j++) {
                STS_F32(b_sts + nbo + (uint32_t)j * AST, bv0[j]);
                STS_F32(b_sts + nbo + (uint32_t)(j + 4) * AST, bv1[j]);
            }
        }
        // prefetch stage s+2
        if (s + 2 < NSTAGE) {
            const int k0 = (s + 2) * BK;
            ra  = *(const float4*)(Ag + k0);
            rb0 = *(const float4*)(Bg + k0);
            rb1 = *(const float4*)(Bg + k0 + 4);
        }

        // compute 8 k-steps from current buffer: per kk, 6 LDS + 32 FFMA2, no MOVs
        #pragma unroll
        for (int kk = 0; kk < BK; kk++) {
            const uint32_t kb = cbo + (uint32_t)kk * AST;
            uint64_t a64[8], b64[4];
            LDS_2U64(a64[0], a64[1], a_lds + kb);          // rows ty*4+0, +1   ({a,a})
            LDS_2U64(a64[2], a64[3], a_lds + kb + 16u);    // rows ty*4+2, +3
            LDS_2U64(a64[4], a64[5], a_lds + kb + 256u);   // rows 32+ty*4+0,+1
            LDS_2U64(a64[6], a64[7], a_lds + kb + 272u);   // rows 32+ty*4+2,+3
            LDS_2U64(b64[0], b64[1], b_lds + kb);          // cols tx*4 +{0,1},{2,3}
            LDS_2U64(b64[2], b64[3], b_lds + kb + 256u);   // cols 64+tx*4 +...
            #pragma unroll
            for (int i = 0; i < 8; i++)
                #pragma unroll
                for (int j = 0; j < 4; j++)
                    FFMA2(acc[i][j], a64[i], b64[j]);
        }
        __syncthreads();
    }

    // ---- epilogue ----
    #pragma unroll
    for (int i = 0; i < 8; i++) {
        const int r = mb + ((i < 4) ? (ty * 4 + i) : (32 + ty * 4 + (i - 4)));
        float* cp = C + (size_t)r * E_EXP + nb;
        #pragma unroll
        for (int j = 0; j < 4; j++) {
            const int c = (j < 2) ? (tx * 4 + 2 * j) : (64 + tx * 4 + 2 * (j - 2));
            const uint32_t lo = (uint32_t)acc[i][j];
            const uint32_t hi = (uint32_t)(acc[i][j] >> 32);
            *(float2*)(cp + c) = make_float2(__uint_as_float(lo), __uint_as_float(hi));
        }
    }
}

// ================= Routing: one warp per token (proven in R2/R8) =================
__global__ __launch_bounds__(256)
void route_kernel(const float* __restrict__ logits,
                  const float* __restrict__ bias,
                  void* __restrict__ w_out,
                  void* __restrict__ idx_out,
                  int mode)
{
    const float NEG_INF = __int_as_float(0xff800000);
    const int warp = threadIdx.x >> 5;
    const int lane = threadIdx.x & 31;
    const int t = blockIdx.x * 8 + warp;
    if (t >= T_TOK) return;

    const float* lp = logits + (size_t)t * E_EXP;

    float s[8], v[8];
    #pragma unroll
    for (int r = 0; r < 8; r++) {
        float z = __ldg(lp + r * 32 + lane);
        float sig = 1.0f / (1.0f + expf(-z));
        s[r] = sig;
        v[r] = sig + __ldg(bias + r * 32 + lane);
    }

    float gsc[8];
    #pragma unroll
    for (int r = 0; r < 8; r++) {
        float m1 = v[r], m2 = NEG_INF;
        #pragma unroll
        for (int off = 16; off; off >>= 1) {
            float o1 = __shfl_xor_sync(0xffffffffu, m1, off);
            float o2 = __shfl_xor_sync(0xffffffffu, m2, off);
            float hi = fmaxf(m1, o1);
            float lo = fminf(m1, o1);
            m2 = fmaxf(lo, fmaxf(m2, o2));
            m1 = hi;
        }
        gsc[r] = m1 + m2;
    }

    unsigned chosen = 0;
    #pragma unroll
    for (int it = 0; it < LG_GRP; it++) {
        float best = NEG_INF; int bg = 0;
        #pragma unroll
        for (int g = 0; g < G_GRP; g++) {
            bool free_g = ((chosen >> g) & 1u) == 0u;
            if (free_g && gsc[g] > best) { best = gsc[g]; bg = g; }
        }
        chosen |= 1u << bg;
    }
    #pragma unroll
    for (int r = 0; r < 8; r++)
        if (!((chosen >> r) & 1u)) v[r] = NEG_INF;

    float my_w = 0.0f;
    int   my_e = 0;
    #pragma unroll
    for (int k = 0; k < K_TOP; k++) {
        float lb = NEG_INF; int lr = 0;
        #pragma unroll
        for (int r = 0; r < 8; r++)
            if (v[r] > lb) { lb = v[r]; lr = r; }
        float bv = lb;
        int be = lr * 32 + lane;
        #pragma unroll
        for (int off = 16; off; off >>= 1) {
            float ov = __shfl_xor_sync(0xffffffffu, bv, off);
            int   oe = __shfl_xor_sync(0xffffffffu, be, off);
            if (ov > bv || (ov == bv && oe < be)) { bv = ov; be = oe; }
        }
        const int wr = be >> 5, wl = be & 31;
        float sv_sel = 0.0f;
        #pragma unroll
        for (int r = 0; r < 8; r++)
            if (r == wr) sv_sel = s[r];
        float ws = __shfl_sync(0xffffffffu, sv_sel, wl);
        if (lane == k) { my_w = ws; my_e = be; }
        if (lane == wl) {
            #pragma unroll
            for (int r = 0; r < 8; r++)
                if (r == wr) v[r] = NEG_INF;
        }
    }

    float wsum = (lane < K_TOP) ? my_w : 0.0f;
    #pragma unroll
    for (int off = 16; off; off >>= 1)
        wsum += __shfl_xor_sync(0xffffffffu, wsum, off);
    float wfin = my_w * (2.5f / wsum);

    if (lane < K_TOP) {
        const size_t o = (size_t)t * K_TOP + lane;
        if (mode == 2) {   // all-f32 concat (JAX promotion, x64 off)
            ((float*)w_out)[o]   = wfin;
            ((float*)idx_out)[o] = (float)my_e;
        } else {           // byte-concat f32 | i64 | i32
            ((float*)w_out)[o]       = wfin;
            ((long long*)idx_out)[o] = (long long)my_e;
        }
        atomicAdd(&g_counts[my_e], 1);
    }
}

__global__ void zero_counts_kernel() { g_counts[threadIdx.x] = 0; }

__global__ void write_counts_kernel(void* __restrict__ cnt_out, int mode) {
    const int e = threadIdx.x;
    if (mode == 2) ((float*)cnt_out)[e] = (float)g_counts[e];
    else           ((int*)cnt_out)[e]   = g_counts[e];
}

// ================= launch =================
extern "C" void kernel_launch(void* const* d_in, const int* in_sizes, int n_in,
                              void* d_out, int out_size)
{
    const float* x    = (const float*)d_in[0];
    const float* W    = (const float*)d_in[1];
    const float* bias = (const float*)d_in[2];

    char* base = (char*)d_out;
    const size_t TK = (size_t)T_TOK * K_TOP;

    int mode;
    void *w_out, *idx_out, *cnt_out;
    if (out_size == (int)(TK + TK + E_EXP)) {
        mode = 2;
        w_out   = base;
        idx_out = base + TK * 4;
        cnt_out = base + 2 * TK * 4;
    } else {
        mode = 0;
        w_out   = base;
        idx_out = base + TK * 4;
        cnt_out = base + TK * 4 + TK * 8;
    }

    zero_counts_kernel<<<1, E_EXP>>>();

    dim3 grid(E_EXP / BN, T_TOK / BM);   // (2, 128) = 256 CTAs, 2/SM -> 1 wave
    gemm_f32x2_kernel<<<grid, 128>>>(x, W, g_logits);

    route_kernel<<<T_TOK / 8, 256>>>(g_logits, bias, w_out, idx_out, mode);
    write_counts_kernel<<<1, E_EXP>>>(cnt_out, mode);
}